// round 4
// baseline (speedup 1.0000x reference)
#include <cuda_runtime.h>
#include <math.h>

// Problem constants (fixed dataset: PMXELoss, seed 0)
#define NQ_  4096
#define NS_  16384
#define D_   128
#define C_   64
#define INFV 1000.0f
#define PSTRIDE 1024   // max supports per class we track (actual = 256)

// Static device scratch (no allocations allowed)
__device__ float g_mus[C_ * D_];        // per-class sums of xs rows
__device__ float g_sscls[C_];           // per-class sum of ||xs_j||^2
__device__ int   g_counts[C_];          // per-class counts
__device__ int   g_perm[C_ * PSTRIDE];  // per-class support index lists
__device__ float g_perq[NQ_];           // per-query (neg_logit - pos_logit)

// ---------------------------------------------------------------------------
__global__ void k_zero() {
    int t = threadIdx.x;
    if (t < C_) g_counts[t] = 0;
}

// Build per-class index lists + counts.
__global__ void k_rank(const int* __restrict__ ys) {
    for (int j = blockIdx.x * blockDim.x + threadIdx.x; j < NS_;
         j += gridDim.x * blockDim.x) {
        int c = ys[j];
        int r = atomicAdd(&g_counts[c], 1);
        if (r < PSTRIDE) g_perm[c * PSTRIDE + r] = j;
    }
}

// One block per class: mu_c[d] = sum of xs rows in class, SS_c = sum of row norms.
__global__ void k_classsum(const float* __restrict__ xs) {
    const int c    = blockIdx.x;
    const int tid  = threadIdx.x;      // 128 threads, thread == dim
    const int lane = tid & 31;
    const int warp = tid >> 5;
    __shared__ float s_red[4];

    int n = g_counts[c];
    if (n > PSTRIDE) n = PSTRIDE;
    const int base = c * PSTRIDE;

    float acc = 0.f, ss = 0.f;
#pragma unroll 4
    for (int r = 0; r < n; ++r) {
        int   j = g_perm[base + r];            // broadcast load
        float v = xs[j * D_ + tid];            // coalesced row load
        acc += v;
        ss  = fmaf(v, v, ss);
    }
    g_mus[c * D_ + tid] = acc;

#pragma unroll
    for (int o = 16; o; o >>= 1) ss += __shfl_xor_sync(0xffffffffu, ss, o);
    if (lane == 0) s_red[warp] = ss;
    __syncthreads();
    if (tid == 0) g_sscls[c] = s_red[0] + s_red[1] + s_red[2] + s_red[3];
}

// One block per query (128 threads, thread == dim).
__global__ void k_query(const float* __restrict__ xq, const int* __restrict__ yq,
                        const float* __restrict__ xs, const int* __restrict__ ys,
                        const int* __restrict__ pos) {
    const int i    = blockIdx.x;
    const int tid  = threadIdx.x;
    const int lane = tid & 31;
    const int warp = tid >> 5;

    __shared__ __align__(16) float s_x[D_];
    __shared__ float s_red[4][4];
    __shared__ float s_norm[C_];

    const int p  = pos[i];       // uniform broadcast loads
    const int cq = ys[p];        // yq_new = ys[pos[i]]

    float x  = xq[i * D_ + tid];
    float xp = xs[p * D_ + tid];
    s_x[tid] = x;

    // leave-one-out prototype for this query's class
    float denom = fmaxf((float)g_counts[cq] - 1.0f, 0.1f);
    float proto = (g_mus[cq * D_ + tid] - x) / denom;
    float dfp   = x - proto;

    // 4 simultaneous warp reductions: qq, ss_pos, dot_pos, ||xq - proto||^2
    float r0 = x * x;
    float r1 = xp * xp;
    float r2 = x * xp;
    float r3 = dfp * dfp;
#pragma unroll
    for (int o = 16; o; o >>= 1) {
        r0 += __shfl_xor_sync(0xffffffffu, r0, o);
        r1 += __shfl_xor_sync(0xffffffffu, r1, o);
        r2 += __shfl_xor_sync(0xffffffffu, r2, o);
        r3 += __shfl_xor_sync(0xffffffffu, r3, o);
    }
    if (lane == 0) {
        s_red[warp][0] = r0; s_red[warp][1] = r1;
        s_red[warp][2] = r2; s_red[warp][3] = r3;
    }
    __syncthreads();
    float qq   = s_red[0][0] + s_red[1][0] + s_red[2][0] + s_red[3][0];
    float ssp  = s_red[0][1] + s_red[1][1] + s_red[2][1] + s_red[3][1];
    float dotp = s_red[0][2] + s_red[1][2] + s_red[2][2] + s_red[3][2];
    float d2   = s_red[0][3] + s_red[1][3] + s_red[2][3] + s_red[3][3];

    float pos_logit  = -sqrtf(fmaxf(d2, 0.f));
    // exact per-pair logit at (i, pos_i), including clamp (T = 1)
    float logit_pair = -0.5f * fmaxf(qq + ssp - 2.f * dotp, 0.f);
    int   yqi        = yq[i];
    float target     = (g_counts[yqi] > 1) ? -INFV : 0.f;
    float delta      = target - logit_pair;   // patch for class cq's sum

    // Per-class summed logits via the clamp-free collapse:
    //   summed_c = -0.5*(cnt_c*qq + SS_c - 2*<xq_i, mu_c>)
    // warp w handles classes w, w+4, ... (16 each); each class: one
    // coalesced 512B row of g_mus (L2-resident), 4 FMAs, warp reduce.
    for (int c = warp; c < C_; c += 4) {
        float4 m  = reinterpret_cast<const float4*>(&g_mus[c * D_])[lane];
        float4 xv = reinterpret_cast<const float4*>(s_x)[lane];
        float dcl = m.x * xv.x + m.y * xv.y + m.z * xv.z + m.w * xv.w;
#pragma unroll
        for (int o = 16; o; o >>= 1) dcl += __shfl_xor_sync(0xffffffffu, dcl, o);
        if (lane == 0) {
            float cnt    = (float)g_counts[c];
            float summed = -0.5f * (cnt * qq + g_sscls[c] - 2.f * dcl);
            if (c == cq) summed += delta;
            s_norm[c] = summed / (cnt - 1.0f);
        }
    }
    __syncthreads();

    // logsumexp over 64 classes (warp 0)
    if (warp == 0) {
        float a  = s_norm[lane];
        float b  = s_norm[lane + 32];
        float mx = fmaxf(a, b);
#pragma unroll
        for (int o = 16; o; o >>= 1)
            mx = fmaxf(mx, __shfl_xor_sync(0xffffffffu, mx, o));
        float e = expf(a - mx) + expf(b - mx);
#pragma unroll
        for (int o = 16; o; o >>= 1) e += __shfl_xor_sync(0xffffffffu, e, o);
        if (lane == 0) g_perq[i] = (mx + logf(e)) - pos_logit;
    }
}

// Mean over queries -> scalar output.
__global__ void k_final(float* __restrict__ out) {
    __shared__ float s[256];
    float acc = 0.f;
    for (int i = threadIdx.x; i < NQ_; i += 256) acc += g_perq[i];
    s[threadIdx.x] = acc;
    __syncthreads();
    for (int o = 128; o; o >>= 1) {
        if (threadIdx.x < o) s[threadIdx.x] += s[threadIdx.x + o];
        __syncthreads();
    }
    if (threadIdx.x == 0) out[0] = s[0] * (1.0f / (float)NQ_);
}

// ---------------------------------------------------------------------------
extern "C" void kernel_launch(void* const* d_in, const int* in_sizes, int n_in,
                              void* d_out, int out_size) {
    const float* xq  = (const float*)d_in[0];   // [NQ, D] f32
    const int*   yq  = (const int*)  d_in[1];   // [NQ]    i32
    const float* xs  = (const float*)d_in[2];   // [NS, D] f32
    const int*   ys  = (const int*)  d_in[3];   // [NS]    i32
    const int*   pos = (const int*)  d_in[4];   // [NQ]    i32
    (void)in_sizes; (void)n_in; (void)out_size;

    k_zero<<<1, 64>>>();
    k_rank<<<32, 256>>>(ys);
    k_classsum<<<C_, 128>>>(xs);
    k_query<<<NQ_, 128>>>(xq, yq, xs, ys, pos);
    k_final<<<1, 256>>>((float*)d_out);
}

// round 5
// speedup vs baseline: 1.9331x; 1.9331x over previous
#include <cuda_runtime.h>
#include <math.h>

// Problem constants (PMXELoss: NQ=4096 queries, NS=16384 supports, D=128, C=64)
#define NQ_  4096
#define NS_  16384
#define D_   128
#define C_   64
#define INFV 1000.0f

#define QBLK 16                      // queries per k_query block (2 per warp, 8 warps)
#define NBLK (NQ_ / QBLK)            // 256 blocks

// Static device scratch (no allocations allowed)
__device__ float4 g_mus4[C_ * (D_ / 4)];  // per-class sums of xs rows (float4 layout)
__device__ float  g_sscls[C_];            // per-class sum of ||xs_j||^2
__device__ float  g_mnorm[C_];            // ||mu_c||^2
__device__ int    g_counts[C_];           // per-class counts
__device__ float  g_bsum[NBLK];           // per-block partial sums of the loss
__device__ int    g_done = 0;             // last-block counter (reset by last block)

__device__ __forceinline__ float dot4(float4 a, float4 b) {
    return a.x * b.x + a.y * b.y + a.z * b.z + a.w * b.w;
}

// ---------------------------------------------------------------------------
// One block per class; 32 warps each scan 512 support rows via ballot and
// accumulate only matching rows. Fully deterministic (fixed order, no atomics).
__global__ void __launch_bounds__(1024) k_classsum(const float4* __restrict__ xs4,
                                                   const int*    __restrict__ ys) {
    const int c    = blockIdx.x;
    const int lane = threadIdx.x & 31;
    const int w    = threadIdx.x >> 5;          // 0..31

    __shared__ float4 s_acc[32][32];
    __shared__ float  s_ss[32];
    __shared__ int    s_cnt[32];

    float4 acc = make_float4(0.f, 0.f, 0.f, 0.f);
    float  ss  = 0.f;
    int    cnt = 0;

    const int base = w * (NS_ / 32);            // 512 rows per warp
#pragma unroll 4
    for (int ch = 0; ch < (NS_ / 32) / 32; ++ch) {   // 16 chunks of 32 rows
        int j0 = base + ch * 32;
        int y  = ys[j0 + lane];
        unsigned m = __ballot_sync(0xffffffffu, y == c);
        cnt += __popc(m);
        while (m) {
            int b = __ffs(m) - 1; m &= m - 1;
            float4 v = xs4[(j0 + b) * 32 + lane];     // coalesced 512B row
            acc.x += v.x; acc.y += v.y; acc.z += v.z; acc.w += v.w;
            ss = fmaf(v.x, v.x, fmaf(v.y, v.y, fmaf(v.z, v.z, fmaf(v.w, v.w, ss))));
        }
    }
    s_acc[w][lane] = acc;
#pragma unroll
    for (int o = 16; o; o >>= 1) ss += __shfl_xor_sync(0xffffffffu, ss, o);
    if (lane == 0) { s_ss[w] = ss; s_cnt[w] = cnt; }   // cnt is warp-uniform
    __syncthreads();

    if (w == 0) {
        float4 t = s_acc[0][lane];
#pragma unroll
        for (int ww = 1; ww < 32; ++ww) {
            float4 u = s_acc[ww][lane];
            t.x += u.x; t.y += u.y; t.z += u.z; t.w += u.w;
        }
        g_mus4[c * 32 + lane] = t;

        float mn  = dot4(t, t);
        float sst = s_ss[lane];
        int   cn  = s_cnt[lane];
#pragma unroll
        for (int o = 16; o; o >>= 1) {
            mn  += __shfl_xor_sync(0xffffffffu, mn, o);
            sst += __shfl_xor_sync(0xffffffffu, sst, o);
            cn  += __shfl_xor_sync(0xffffffffu, cn, o);
        }
        if (lane == 0) { g_mnorm[c] = mn; g_sscls[c] = sst; g_counts[c] = cn; }
    }
}

// ---------------------------------------------------------------------------
// 256 blocks x 256 threads. Each warp handles TWO queries (register tiling so
// every g_mus load feeds 8 FMAs). Per-class logits via the clamp-free collapse:
//   normalized_c = dot(x, mu_c) * inv_c + A_c*qq + B_c,
//   A_c = -0.5*cnt_c*inv_c, B_c = -0.5*SS_c*inv_c, inv_c = 1/(cnt_c-1),
// with the (i, pos_i) entry patched exactly (clamp + -INF overwrite).
// Prototype distance computed analytically from dot(x, mu_cq) and ||mu_cq||^2.
// Final mean fused via last-block reduction.
__global__ void __launch_bounds__(256) k_query(
    const float4* __restrict__ xq4, const int* __restrict__ yq,
    const float4* __restrict__ xs4, const int* __restrict__ ys,
    const int* __restrict__ pos, float* __restrict__ out)
{
    const int lane = threadIdx.x & 31;
    const int w    = threadIdx.x >> 5;          // 0..7
    const int q0   = blockIdx.x * QBLK + w * 2;
    const int q1   = q0 + 1;

    __shared__ float s_v[8][2][C_];             // raw class dots per warp/query
    __shared__ float s_res[QBLK];
    __shared__ int   s_last;

    float4 xa = xq4[q0 * 32 + lane];
    float4 xb = xq4[q1 * 32 + lane];
    const int p0 = pos[q0], p1 = pos[q1];
    float4 xpa = xs4[p0 * 32 + lane];
    float4 xpb = xs4[p1 * 32 + lane];

    // 6 simultaneous warp reductions
    float qq0 = dot4(xa, xa),  qq1 = dot4(xb, xb);
    float sp0 = dot4(xpa, xpa), sp1 = dot4(xpb, xpb);
    float dp0 = dot4(xa, xpa),  dp1 = dot4(xb, xpb);
#pragma unroll
    for (int o = 16; o; o >>= 1) {
        qq0 += __shfl_xor_sync(0xffffffffu, qq0, o);
        qq1 += __shfl_xor_sync(0xffffffffu, qq1, o);
        sp0 += __shfl_xor_sync(0xffffffffu, sp0, o);
        sp1 += __shfl_xor_sync(0xffffffffu, sp1, o);
        dp0 += __shfl_xor_sync(0xffffffffu, dp0, o);
        dp1 += __shfl_xor_sync(0xffffffffu, dp1, o);
    }

    // 64 class dots for both queries; one mu load feeds 8 FMAs
    const bool l0 = (lane == 0);
#pragma unroll 4
    for (int c = 0; c < C_; ++c) {
        float4 m  = g_mus4[c * 32 + lane];
        float  d0 = dot4(m, xa);
        float  d1 = dot4(m, xb);
#pragma unroll
        for (int o = 16; o; o >>= 1) {
            d0 += __shfl_xor_sync(0xffffffffu, d0, o);
            d1 += __shfl_xor_sync(0xffffffffu, d1, o);
        }
        if (l0) { s_v[w][0][c] = d0; s_v[w][1][c] = d1; }
    }
    __syncwarp();

    // per-query scalars (warp-uniform)
    const int cq0 = ys[p0], cq1 = ys[p1];
    const int yqi0 = yq[q0], yqi1 = yq[q1];
    float cnq0 = (float)g_counts[cq0], cnq1 = (float)g_counts[cq1];
    float den0 = fmaxf(cnq0 - 1.f, 0.1f), den1 = fmaxf(cnq1 - 1.f, 0.1f);

    float lp0 = -0.5f * fmaxf(qq0 + sp0 - 2.f * dp0, 0.f);   // exact pair logit
    float lp1 = -0.5f * fmaxf(qq1 + sp1 - 2.f * dp1, 0.f);
    float dl0 = ((g_counts[yqi0] > 1) ? -INFV : 0.f) - lp0;  // bucket patch
    float dl1 = ((g_counts[yqi1] > 1) ? -INFV : 0.f) - lp1;

    // pos_logit: ||x - proto||^2 = (e^2*qq - 2e*dot(x,mu) + ||mu||^2)/den^2, e=den+1
    float dm0 = s_v[w][0][cq0], dm1 = s_v[w][1][cq1];
    float e0 = den0 + 1.f, e1 = den1 + 1.f;
    float d20 = (e0 * e0 * qq0 - 2.f * e0 * dm0 + g_mnorm[cq0]) / (den0 * den0);
    float d21 = (e1 * e1 * qq1 - 2.f * e1 * dm1 + g_mnorm[cq1]) / (den1 * den1);
    float plog0 = -sqrtf(fmaxf(d20, 0.f));
    float plog1 = -sqrtf(fmaxf(d21, 0.f));

    // per-lane class params: lane handles classes lane and lane+32
    int   cl = g_counts[lane],      chh = g_counts[lane + 32];
    float sl = g_sscls[lane],       shh = g_sscls[lane + 32];
    float il = 1.f / ((float)cl - 1.f);
    float ih = 1.f / ((float)chh - 1.f);
    float Al = -0.5f * (float)cl * il,  Bl = -0.5f * sl * il;
    float Ah = -0.5f * (float)chh * ih, Bh = -0.5f * shh * ih;

    // q0: normalized values + LSE
    float v0l = fmaf(s_v[w][0][lane],      il, fmaf(Al, qq0, Bl));
    float v0h = fmaf(s_v[w][0][lane + 32], ih, fmaf(Ah, qq0, Bh));
    if (lane == (cq0 & 31)) { if (cq0 < 32) v0l += dl0 * il; else v0h += dl0 * ih; }
    float v1l = fmaf(s_v[w][1][lane],      il, fmaf(Al, qq1, Bl));
    float v1h = fmaf(s_v[w][1][lane + 32], ih, fmaf(Ah, qq1, Bh));
    if (lane == (cq1 & 31)) { if (cq1 < 32) v1l += dl1 * il; else v1h += dl1 * ih; }

    float mx0 = fmaxf(v0l, v0h), mx1 = fmaxf(v1l, v1h);
#pragma unroll
    for (int o = 16; o; o >>= 1) {
        mx0 = fmaxf(mx0, __shfl_xor_sync(0xffffffffu, mx0, o));
        mx1 = fmaxf(mx1, __shfl_xor_sync(0xffffffffu, mx1, o));
    }
    float ex0 = expf(v0l - mx0) + expf(v0h - mx0);
    float ex1 = expf(v1l - mx1) + expf(v1h - mx1);
#pragma unroll
    for (int o = 16; o; o >>= 1) {
        ex0 += __shfl_xor_sync(0xffffffffu, ex0, o);
        ex1 += __shfl_xor_sync(0xffffffffu, ex1, o);
    }
    if (l0) {
        s_res[w * 2]     = (mx0 + logf(ex0)) - plog0;
        s_res[w * 2 + 1] = (mx1 + logf(ex1)) - plog1;
    }
    __syncthreads();

    // fused final reduction (last-block pattern)
    if (threadIdx.x == 0) {
        float t = 0.f;
#pragma unroll
        for (int i = 0; i < QBLK; ++i) t += s_res[i];
        g_bsum[blockIdx.x] = t;
        __threadfence();
        int old = atomicAdd(&g_done, 1);
        s_last = (old == (int)gridDim.x - 1);
    }
    __syncthreads();
    if (s_last) {
        __threadfence();
        __shared__ float s_f[NBLK];
        float t;
        asm volatile("ld.global.cg.f32 %0, [%1];" : "=f"(t) : "l"(&g_bsum[threadIdx.x]));
        s_f[threadIdx.x] = t;
        __syncthreads();
#pragma unroll
        for (int o = 128; o; o >>= 1) {
            if ((int)threadIdx.x < o) s_f[threadIdx.x] += s_f[threadIdx.x + o];
            __syncthreads();
        }
        if (threadIdx.x == 0) {
            out[0]  = s_f[0] * (1.0f / (float)NQ_);
            g_done  = 0;                      // reset for next graph replay
        }
    }
}

// ---------------------------------------------------------------------------
extern "C" void kernel_launch(void* const* d_in, const int* in_sizes, int n_in,
                              void* d_out, int out_size) {
    const float4* xq4 = (const float4*)d_in[0];   // [NQ, D] f32
    const int*    yqp = (const int*)   d_in[1];   // [NQ]    i32
    const float4* xs4 = (const float4*)d_in[2];   // [NS, D] f32
    const int*    ysp = (const int*)   d_in[3];   // [NS]    i32
    const int*    pop = (const int*)   d_in[4];   // [NQ]    i32
    (void)in_sizes; (void)n_in; (void)out_size;

    k_classsum<<<C_, 1024>>>(xs4, ysp);
    k_query<<<NBLK, 256>>>(xq4, yqp, xs4, ysp, pop, (float*)d_out);
}